// round 1
// baseline (speedup 1.0000x reference)
#include <cuda_runtime.h>

// LogicalConsistencyLoss: out = 0.5 * (S_lin + S_abs) / (R*B)
//   S_abs = sum_{s,a,b,c} |M_ab - M_ac*M_bc|
//   S_lin = sum_s [ N * sum(M) - sum_c (colsum_c)^2 ]
// where M = sigmoid(logits) * mask_a * mask_b per (batch, relation) slice.

#define B_ 2
#define N_ 512
#define R_ 4
#define S_ (B_ * R_)          // 8 slices
#define NT (N_ / 128)         // 4 tiles per dim
#define CSPLIT 4
#define NPART (NT * NT * CSPLIT * S_)  // 512 partials

__device__ float  g_rel[S_ * N_ * N_];   // 8 MB scratch: [slice][a][b]
__device__ float  g_part[NPART];
__device__ double g_lin[S_];

// ---------------- Pass 1: sigmoid + mask, de-interleave R ----------------
__global__ void sigmoid_mask_kernel(const float* __restrict__ logits,
                                    const int*   __restrict__ masks) {
    int idx = blockIdx.x * blockDim.x + threadIdx.x;  // over B*N*N
    if (idx >= B_ * N_ * N_) return;
    int b   = idx / (N_ * N_);
    int rem = idx - b * (N_ * N_);
    int i   = rem / N_;
    int j   = rem - i * N_;
    float mm = (masks[b * N_ + i] > 0 && masks[b * N_ + j] > 0) ? 1.0f : 0.0f;
    float4 v = ((const float4*)logits)[idx];  // 4 relations of one (b,i,j)
    float p0 = mm / (1.0f + __expf(-v.x));
    float p1 = mm / (1.0f + __expf(-v.y));
    float p2 = mm / (1.0f + __expf(-v.z));
    float p3 = mm / (1.0f + __expf(-v.w));
    g_rel[(b * R_ + 0) * N_ * N_ + rem] = p0;
    g_rel[(b * R_ + 1) * N_ * N_ + rem] = p1;
    g_rel[(b * R_ + 2) * N_ * N_ + rem] = p2;
    g_rel[(b * R_ + 3) * N_ * N_ + rem] = p3;
}

// ---------------- Pass 2: cubic |.| contraction, SGEMM-style ----------------
// Grid: x = (a,b) tile (16), y = c-split (4), z = slice (8). 256 threads.
// Each thread: 8x8 register tile of M_ab, 8 running accumulators.
__global__ void __launch_bounds__(256)
trans_abs_kernel() {
    const int tile = blockIdx.x;      // 0..15
    const int cblk = blockIdx.y;      // 0..3
    const int sl   = blockIdx.z;      // 0..7
    const float* __restrict__ M = g_rel + sl * N_ * N_;

    const int a0 = (tile / NT) * 128;
    const int b0 = (tile % NT) * 128;
    const int c0 = cblk * (N_ / CSPLIT);

    const int tid = threadIdx.x;
    const int tx  = tid & 15;         // b sub-tile
    const int ty  = tid >> 4;         // a sub-tile

    // Load 8x8 M_ab register tile (resident for the whole c loop)
    float mab[8][8];
#pragma unroll
    for (int i = 0; i < 8; ++i) {
        const float4* row = (const float4*)(M + (a0 + ty * 8 + i) * N_ + b0 + tx * 8);
        float4 p0 = row[0];
        float4 p1 = row[1];
        mab[i][0] = p0.x; mab[i][1] = p0.y; mab[i][2] = p0.z; mab[i][3] = p0.w;
        mab[i][4] = p1.x; mab[i][5] = p1.y; mab[i][6] = p1.z; mab[i][7] = p1.w;
    }

    __shared__ float sA[8][128];   // [c within chunk][a]
    __shared__ float sB[8][128];   // [c within chunk][b]

    float acc[8];
#pragma unroll
    for (int j = 0; j < 8; ++j) acc[j] = 0.0f;

    const int r   = tid >> 1;         // 0..127: row within tile to stage
    const int cof = (tid & 1) * 4;    // which 4 c's

    for (int cc = c0; cc < c0 + N_ / CSPLIT; cc += 8) {
        float4 va = *(const float4*)(M + (a0 + r) * N_ + cc + cof);
        float4 vb = *(const float4*)(M + (b0 + r) * N_ + cc + cof);
        __syncthreads();   // previous chunk's compute done before overwrite
        sA[cof + 0][r] = va.x; sA[cof + 1][r] = va.y;
        sA[cof + 2][r] = va.z; sA[cof + 3][r] = va.w;
        sB[cof + 0][r] = vb.x; sB[cof + 1][r] = vb.y;
        sB[cof + 2][r] = vb.z; sB[cof + 3][r] = vb.w;
        __syncthreads();

#pragma unroll
        for (int c = 0; c < 8; ++c) {
            float ua[8], ub[8];
            float4 t0 = *(const float4*)&sA[c][ty * 8];
            float4 t1 = *(const float4*)&sA[c][ty * 8 + 4];
            ua[0] = t0.x; ua[1] = t0.y; ua[2] = t0.z; ua[3] = t0.w;
            ua[4] = t1.x; ua[5] = t1.y; ua[6] = t1.z; ua[7] = t1.w;
            float4 u0 = *(const float4*)&sB[c][tx * 8];
            float4 u1 = *(const float4*)&sB[c][tx * 8 + 4];
            ub[0] = u0.x; ub[1] = u0.y; ub[2] = u0.z; ub[3] = u0.w;
            ub[4] = u1.x; ub[5] = u1.y; ub[6] = u1.z; ub[7] = u1.w;
#pragma unroll
            for (int i = 0; i < 8; ++i) {
#pragma unroll
                for (int j = 0; j < 8; ++j) {
                    // FFMA (neg modifier) + FADD with |.| source modifier:
                    // exactly 2 fma-pipe instructions per element.
                    float t = fmaf(-ua[i], ub[j], mab[i][j]);
                    acc[j] += fabsf(t);
                }
            }
        }
    }

    // Deterministic block reduction: warp shfl, then smem across 8 warps.
    float tsum = 0.0f;
#pragma unroll
    for (int j = 0; j < 8; ++j) tsum += acc[j];
#pragma unroll
    for (int off = 16; off > 0; off >>= 1)
        tsum += __shfl_down_sync(0xFFFFFFFFu, tsum, off);

    __shared__ float wred[8];
    if ((tid & 31) == 0) wred[tid >> 5] = tsum;
    __syncthreads();
    if (tid == 0) {
        float s = 0.0f;
#pragma unroll
        for (int w = 0; w < 8; ++w) s += wred[w];
        g_part[(sl * CSPLIT + cblk) * (NT * NT) + tile] = s;
    }
}

// ---------------- Pass 3: linear correction per slice ----------------
__global__ void colsum_kernel() {
    const int sl = blockIdx.x;
    const int c  = threadIdx.x;  // 512 threads = one per column
    const float* __restrict__ M = g_rel + sl * N_ * N_;
    float s = 0.0f;
#pragma unroll 8
    for (int a = 0; a < N_; ++a) s += M[a * N_ + c];

    __shared__ double sh1[N_];
    __shared__ double sh2[N_];
    sh1[c] = (double)s;
    sh2[c] = (double)s * (double)s;
    __syncthreads();
    for (int st = N_ / 2; st > 0; st >>= 1) {
        if (c < st) { sh1[c] += sh1[c + st]; sh2[c] += sh2[c + st]; }
        __syncthreads();
    }
    if (c == 0) g_lin[sl] = (double)N_ * sh1[0] - sh2[0];
}

// ---------------- Pass 4: deterministic final combine ----------------
__global__ void final_kernel(float* __restrict__ out) {
    __shared__ double sh[NPART];
    const int t = threadIdx.x;
    sh[t] = (double)g_part[t];
    __syncthreads();
    for (int s = NPART / 2; s > 0; s >>= 1) {
        if (t < s) sh[t] += sh[t + s];
        __syncthreads();
    }
    if (t == 0) {
        double slin = 0.0;
#pragma unroll
        for (int k = 0; k < S_; ++k) slin += g_lin[k];
        out[0] = (float)(0.5 * (sh[0] + slin) / (double)(R_ * B_));
    }
}

extern "C" void kernel_launch(void* const* d_in, const int* in_sizes, int n_in,
                              void* d_out, int out_size) {
    const float* logits = (const float*)d_in[0];
    const int*   masks  = (const int*)d_in[1];
    float*       out    = (float*)d_out;

    sigmoid_mask_kernel<<<(B_ * N_ * N_ + 255) / 256, 256>>>(logits, masks);

    dim3 g2(NT * NT, CSPLIT, S_);
    trans_abs_kernel<<<g2, 256>>>();

    colsum_kernel<<<S_, N_>>>();
    final_kernel<<<1, NPART>>>(out);
}